// round 17
// baseline (speedup 1.0000x reference)
#include <cuda_runtime.h>
#include <cuda_bf16.h>
#include <math.h>
#include <stdint.h>

// ---------------------------------------------------------------------------
// SemanticConsistencyLoss — R17: single-kernel. Accum main loop byte-identical
// to R16 (measured best). The Frobenius-norm finale is ticket-folded into the
// last-finishing accum CTA (reads 307 KB L2-resident g_sums/g_cnt, fixed-order
// d^2 partials + block tree, sqrt -> out), then resets all device state for
// the next graph replay. Removes the second kernel launch + ramp (~6 us).
// ---------------------------------------------------------------------------

#define NUM_CLASSES 150
#define CH        256
#define HCH       128
#define NPIX      (512 * 512)
#define CHUNKS    74
#define PPC       3584            // 74*3584 >= NPIX, multiple of 32
#define TPX       32
#define TPB       512
#define TSTRIDE   33
#define TILE_W    (HCH * TSTRIDE) // 4224 words per buffer
#define NCTA      (CHUNKS * 2 * 2)

__device__ float g_sums[2][NUM_CLASSES][CH];   // zero-initialized statics
__device__ int   g_cnt[2][NUM_CLASSES];
__device__ unsigned int g_ticket = 0;

// smem floats: tile[2][4224] | lbl[3584] | cnt[152]
#define SM_LBL      (2 * TILE_W)
#define SM_CNT      (SM_LBL + PPC)
#define SMEM_FLOATS (SM_CNT + 152)
#define SMEM_BYTES  (SMEM_FLOATS * 4)   // ~48.7 KB -> occ 2

#define ACC_CASE(k)                                                        \
    case k: acc[k].x += v0; acc[k].y += v1; acc[k].z += v2; acc[k].w += v3; break;

__global__ void __launch_bounds__(TPB, 2)
accum_kernel(const float* __restrict__ src, const float* __restrict__ trg,
             const int* __restrict__ slab, const int* __restrict__ tlab,
             float* __restrict__ out) {
    extern __shared__ float smf[];
    float* tiles = smf;                 // [2][128][33]
    int*   lbl_s = (int*)(smf + SM_LBL);
    int*   cnt   = (int*)(smf + SM_CNT);

    const int chunk = blockIdx.x;
    const int tsel  = blockIdx.y;
    const int chalf = blockIdx.z;
    const float* __restrict__ F =
        (tsel ? trg : src) + (size_t)chalf * HCH * NPIX;
    const int*   __restrict__ L = tsel ? tlab : slab;

    const int tid  = threadIdx.x;
    const int wid  = tid >> 5;          // owns labels lab&15 == wid
    const int lane = tid & 31;

    if (tid < NUM_CLASSES) cnt[tid] = 0;
    __syncthreads();

    const int pbase  = chunk * PPC;
    const int psz    = min(PPC, NPIX - pbase);
    const int ntiles = psz / TPX;       // 112 (last chunk: 16)

    // ---- cache labels in smem + histogram (integer-exact) ----
    for (int i = tid; i < psz; i += TPB) {
        int l = L[pbase + i];
        lbl_s[i] = l;
        if (chalf == 0) atomicAdd(&cnt[l], 1);
    }
    __syncthreads();

    // counts -> global (integer atomics, order-exact)
    if (chalf == 0 && tid < NUM_CLASSES)
        atomicAdd(&g_cnt[tsel][tid], cnt[tid]);

    // ---- register accumulators: class 16k+wid, channels lane+{0,32,64,96} ----
    float4 acc[10];
#pragma unroll
    for (int k = 0; k < 10; ++k) acc[k] = make_float4(0.f, 0.f, 0.f, 0.f);

    // ---- register prefetch of tile 0 ----
    float4 r[2];
    int mylbl;
    {
#pragma unroll
        for (int i = 0; i < 2; ++i) {
            int q = tid + TPB * i;
            int ch = q >> 3, p4 = q & 7;
            r[i] = *(const float4*)(F + (size_t)ch * NPIX + pbase + p4 * 4);
        }
        mylbl = lbl_s[lane];
    }

    for (int t = 0; t < ntiles; ++t) {
        float* tb = tiles + (t & 1) * TILE_W;

        // ---- stage: bank-perfect scalar stores ----
#pragma unroll
        for (int i = 0; i < 2; ++i) {
            int q = tid + TPB * i;
            int ch = q >> 3, p4 = q & 7;
            float* d = tb + ch * TSTRIDE + p4 * 4;
            d[0] = r[i].x; d[1] = r[i].y; d[2] = r[i].z; d[3] = r[i].w;
        }
        const int lblcur = mylbl;
        __syncthreads();   // one barrier per tile (double buffer -> safe)

        // ---- prefetch next tile (label from smem: short latency) ----
        if (t + 1 < ntiles) {
            const int p0 = pbase + (t + 1) * TPX;
#pragma unroll
            for (int i = 0; i < 2; ++i) {
                int q = tid + TPB * i;
                int ch = q >> 3, p4 = q & 7;
                r[i] = *(const float4*)(F + (size_t)ch * NPIX + p0 + p4 * 4);
            }
            mylbl = lbl_s[(t + 1) * TPX + lane];
        }

        // ---- accumulate into registers: warp-uniform class switch ----
        unsigned m = __ballot_sync(0xffffffffu, (lblcur & 15) == wid);
        while (m) {
            const int j = __ffs(m) - 1;
            m &= m - 1;
            const int row = __shfl_sync(0xffffffffu, lblcur, j);
            const float* srcc = tb + lane * TSTRIDE + j;   // bank = lane+j
            const float v0 = srcc[0];
            const float v1 = srcc[32 * TSTRIDE];
            const float v2 = srcc[64 * TSTRIDE];
            const float v3 = srcc[96 * TSTRIDE];
            switch (row >> 4) {        // warp-uniform branch
                ACC_CASE(0) ACC_CASE(1) ACC_CASE(2) ACC_CASE(3) ACC_CASE(4)
                ACC_CASE(5) ACC_CASE(6) ACC_CASE(7) ACC_CASE(8) ACC_CASE(9)
            }
        }
    }

    // ---- epilogue: registers -> global sums via coalesced float REDG ----
    const int nk = (wid < 6) ? 10 : 9;   // classes 16k+wid <= 149
#pragma unroll
    for (int k = 0; k < 10; ++k) {
        if (k < nk) {
            const int cls = 16 * k + wid;
            float* o = &g_sums[tsel][cls][chalf * HCH];
            atomicAdd(o + lane,      acc[k].x);
            atomicAdd(o + lane + 32, acc[k].y);
            atomicAdd(o + lane + 64, acc[k].z);
            atomicAdd(o + lane + 96, acc[k].w);
        }
    }

    // ---- ticket: last CTA computes the norm and resets state ----
    __shared__ unsigned int s_last;
    __threadfence();
    __syncthreads();
    if (tid == 0) {
        unsigned int tk = atomicAdd(&g_ticket, 1u);
        s_last = (tk == (unsigned)(NCTA - 1)) ? 1u : 0u;
    }
    __syncthreads();
    if (!s_last) return;

    // --- finale (cold path, one CTA): fixed-order d^2 partials ---
    float part = 0.0f;
    for (int i = tid; i < NUM_CLASSES * CH; i += TPB) {
        const int cls = i >> 8;
        const int ch  = i & 255;
        const float ss  = __ldcg(&g_sums[0][cls][ch]);
        const float st  = __ldcg(&g_sums[1][cls][ch]);
        const float cs  = (float)__ldcg(&g_cnt[0][cls]);
        const float ctn = (float)__ldcg(&g_cnt[1][cls]);
        const float d = ss / (cs + 1e-8f) - st / (ctn + 1e-8f);
        part += d * d;
        g_sums[0][cls][ch] = 0.0f;      // reset for next replay
        g_sums[1][cls][ch] = 0.0f;
    }
    if (tid < 2 * NUM_CLASSES)
        ((int*)g_cnt)[tid] = 0;

    float* red = smf;                   // reuse tile smem
    red[tid] = part;
    __syncthreads();
#pragma unroll
    for (int s = TPB / 2; s > 0; s >>= 1) {
        if (tid < s) red[tid] += red[tid + s];
        __syncthreads();
    }
    if (tid == 0) {
        out[0] = sqrtf(red[0]);
        g_ticket = 0;                   // reset for next graph replay
    }
}

extern "C" void kernel_launch(void* const* d_in, const int* in_sizes, int n_in,
                              void* d_out, int out_size) {
    const float* src = (const float*)d_in[0];   // src_fea  [1,256,512,512] f32
    const float* trg = (const float*)d_in[1];   // trg_fea
    const int*   sl  = (const int*)d_in[2];     // src_labels [1,512,512] i32
    const int*   tl  = (const int*)d_in[3];     // trg_pseudo_labels
    float* out = (float*)d_out;

    cudaFuncSetAttribute(accum_kernel,
                         cudaFuncAttributeMaxDynamicSharedMemorySize,
                         SMEM_BYTES);

    dim3 grid(CHUNKS, 2, 2);   // 296 CTAs = one wave at occ 2
    accum_kernel<<<grid, TPB, SMEM_BYTES>>>(src, trg, sl, tl, out);
}